// round 6
// baseline (speedup 1.0000x reference)
#include <cuda_runtime.h>
#include <cstdint>

#define NGROUPS 8
#define NTHREADS 256

__global__ void __launch_bounds__(NTHREADS)
fd_sample_kernel(const float* __restrict__ q0,
                 const float* __restrict__ qg,
                 const float* __restrict__ noise0,
                 const float* __restrict__ noise,
                 float* __restrict__ out,
                 int n)
{
    // Stage tiny probability tables in shared memory (456 floats).
    __shared__ float s_q0[8];
    __shared__ float s_qg[(NGROUPS - 1) * 64];
    for (int t = threadIdx.x; t < 8; t += NTHREADS) s_q0[t] = q0[t];
    for (int t = threadIdx.x; t < (NGROUPS - 1) * 64; t += NTHREADS) s_qg[t] = qg[t];
    __syncthreads();

    int i = blockIdx.x * NTHREADS + threadIdx.x;
    if (i >= n) return;

    // ---- prefetch ALL noise for this sample: 16 independent LDG.128 ----
    // __ldcs = evict-first streaming loads (no reuse anywhere in this kernel)
    float4 vv[2 * NGROUPS];
    {
        const float4* p0 = reinterpret_cast<const float4*>(noise0) + (size_t)i * 2;
        vv[0] = __ldcs(p0 + 0);
        vv[1] = __ldcs(p0 + 1);
        const size_t gstride = (size_t)n * 8;   // floats per group in `noise`
#pragma unroll
        for (int g = 0; g < NGROUPS - 1; g++) {
            const float4* pg =
                reinterpret_cast<const float4*>(noise + (size_t)g * gstride) + (size_t)i * 2;
            vv[2 + g * 2] = __ldcs(pg + 0);
            vv[3 + g * 2] = __ldcs(pg + 1);
        }
    }

    // ---- chained Gumbel-max argmax; pack 3 bits/group into one integer ----
    unsigned int packed = 0;   // bit (23 - (g*3+k)) holds output column g*3+k
    int best = 0;
#pragma unroll
    for (int g = 0; g < NGROUPS; g++) {
        // group 0 uses q0; group g>=1 uses conditional slice qg[g-1][best]
        // (previous argmax index IS the flattened C-order conditioning index)
        const float* tbl = (g == 0) ? s_q0 : &s_qg[(g - 1) * 64 + best * 8];
        float4 a = vv[g * 2 + 0];
        float4 b = vv[g * 2 + 1];
        float v[8];
        v[0] = a.x; v[1] = a.y; v[2] = a.z; v[3] = a.w;
        v[4] = b.x; v[5] = b.y; v[6] = b.z; v[7] = b.w;

        int nb = 0;
        float nbv = v[0] + tbl[0];
#pragma unroll
        for (int j = 1; j < 8; j++) {
            float x = v[j] + tbl[j];
            if (x > nbv) { nbv = x; nb = j; }   // strict > == first-max (jnp.argmax)
        }
        best = nb;
        packed = (packed << 3) | (unsigned int)best;  // appends b2,b1,b0 in order
    }

    // ---- expand 24 packed bits -> 24 floats, write as 6 x float4 ----
    float4* po = reinterpret_cast<float4*>(out + (size_t)i * 24);
#pragma unroll
    for (int k = 0; k < 6; k++) {
        float4 w;
        w.x = (float)((packed >> (23 - (k * 4 + 0))) & 1u);
        w.y = (float)((packed >> (23 - (k * 4 + 1))) & 1u);
        w.z = (float)((packed >> (23 - (k * 4 + 2))) & 1u);
        w.w = (float)((packed >> (23 - (k * 4 + 3))) & 1u);
        __stcs(po + k, w);   // streaming store, evict-first
    }
}

extern "C" void kernel_launch(void* const* d_in, const int* in_sizes, int n_in,
                              void* d_out, int out_size)
{
    // Identify inputs by element count — robust to harness input ordering.
    //   q0:      8 floats
    //   qg:      (G-1)*64 = 448 floats
    //   noise0:  N*8 floats
    //   noise:   (G-1)*N*8 floats  (the largest array)
    const float* q0 = nullptr;
    const float* qg = nullptr;
    const float* noise0 = nullptr;
    const float* noise = nullptr;
    long long n0_sz = 0;

    for (int k = 0; k < n_in; k++) {
        long long sz = in_sizes[k];
        const float* p = (const float*)d_in[k];
        if (sz == 8) {
            q0 = p;
        } else if (sz == (NGROUPS - 1) * 64) {
            qg = p;
        } else {
            if (noise0 == nullptr) { noise0 = p; n0_sz = sz; }
            else if (sz > n0_sz)   { noise = p; }
            else { noise = noise0; noise0 = p; n0_sz = sz; }
        }
    }

    const int n = (int)(n0_sz / 8);   // N samples
    const int blocks = (n + NTHREADS - 1) / NTHREADS;
    fd_sample_kernel<<<blocks, NTHREADS>>>(q0, qg, noise0, noise,
                                           (float*)d_out, n);
}

// round 7
// speedup vs baseline: 1.0075x; 1.0075x over previous
#include <cuda_runtime.h>
#include <cstdint>

#define NGROUPS 8
#define NTHREADS 128
#define CHUNK_FLOATS (NTHREADS * 8)   // 1024 floats = 4KB per group per block

__global__ void __launch_bounds__(NTHREADS)
fd_sample_kernel(const float* __restrict__ q0,
                 const float* __restrict__ qg,
                 const float* __restrict__ noise0,
                 const float* __restrict__ noise,
                 float* __restrict__ out,
                 int n)
{
    __shared__ float s_noise[NGROUPS][CHUNK_FLOATS];       // 32 KB
    __shared__ float s_q0[8];
    __shared__ float s_qg[(NGROUPS - 1) * 64];
    __shared__ __align__(8) unsigned long long s_mbar;

    const int t = threadIdx.x;
    const int block_start = blockIdx.x * NTHREADS;
    const int nrem = min(NTHREADS, n - block_start);       // samples this block
    const unsigned int chunk_bytes = (unsigned int)nrem * 32u;  // mult of 16

    const uint32_t mbar_addr = (uint32_t)__cvta_generic_to_shared(&s_mbar);

    if (t == 0) {
        asm volatile("mbarrier.init.shared.b64 [%0], %1;"
                     :: "r"(mbar_addr), "r"(1) : "memory");
    }
    __syncthreads();   // mbarrier init visible before any complete_tx lands

    if (t == 0) {
        asm volatile("mbarrier.arrive.expect_tx.shared.b64 _, [%0], %1;"
                     :: "r"(mbar_addr), "r"(chunk_bytes * NGROUPS) : "memory");
        // group 0 stream: noise0
        {
            uint32_t dst = (uint32_t)__cvta_generic_to_shared(&s_noise[0][0]);
            const float* src = noise0 + (size_t)block_start * 8;
            asm volatile(
                "cp.async.bulk.shared::cta.global.mbarrier::complete_tx::bytes "
                "[%0], [%1], %2, [%3];"
                :: "r"(dst), "l"(src), "r"(chunk_bytes), "r"(mbar_addr) : "memory");
        }
        // group 1..7 streams: noise[(g-1)]
        const size_t gstride = (size_t)n * 8;
#pragma unroll
        for (int g = 1; g < NGROUPS; g++) {
            uint32_t dst = (uint32_t)__cvta_generic_to_shared(&s_noise[g][0]);
            const float* src = noise + (size_t)(g - 1) * gstride + (size_t)block_start * 8;
            asm volatile(
                "cp.async.bulk.shared::cta.global.mbarrier::complete_tx::bytes "
                "[%0], [%1], %2, [%3];"
                :: "r"(dst), "l"(src), "r"(chunk_bytes), "r"(mbar_addr) : "memory");
        }
    }

    // Stage tiny tables with plain loads while the bulk copies are in flight.
    for (int k = t; k < 8; k += NTHREADS) s_q0[k] = q0[k];
    for (int k = t; k < (NGROUPS - 1) * 64; k += NTHREADS) s_qg[k] = qg[k];
    __syncthreads();   // tables visible to all threads

    // Wait for all 8 bulk copies (phase 0), acquire so smem reads are ordered.
    {
        unsigned int done;
        asm volatile(
            "{\n\t.reg .pred p;\n\t"
            "mbarrier.try_wait.parity.acquire.cta.shared::cta.b64 p, [%1], %2;\n\t"
            "selp.b32 %0, 1, 0, p;\n\t}"
            : "=r"(done) : "r"(mbar_addr), "r"(0) : "memory");
        while (!done) {
            asm volatile(
                "{\n\t.reg .pred p;\n\t"
                "mbarrier.try_wait.parity.acquire.cta.shared::cta.b64 p, [%1], %2, 0x989680;\n\t"
                "selp.b32 %0, 1, 0, p;\n\t}"
                : "=r"(done) : "r"(mbar_addr), "r"(0) : "memory");
        }
    }

    if (t < nrem) {
        // ---- chained Gumbel-max argmax over the 8 groups, from smem ----
        unsigned int packed = 0;
        int best = 0;
#pragma unroll
        for (int g = 0; g < NGROUPS; g++) {
            // group 0 uses q0; group g>=1 uses conditional slice qg[g-1][best]
            const float* tbl = (g == 0) ? s_q0 : &s_qg[(g - 1) * 64 + best * 8];
            const float4* pv = reinterpret_cast<const float4*>(&s_noise[g][t * 8]);
            float4 a = pv[0];
            float4 b = pv[1];
            float v[8];
            v[0] = a.x; v[1] = a.y; v[2] = a.z; v[3] = a.w;
            v[4] = b.x; v[5] = b.y; v[6] = b.z; v[7] = b.w;

            int nb = 0;
            float nbv = v[0] + tbl[0];
#pragma unroll
            for (int j = 1; j < 8; j++) {
                float x = v[j] + tbl[j];
                if (x > nbv) { nbv = x; nb = j; }   // strict > == first-max
            }
            best = nb;
            packed = (packed << 3) | (unsigned int)best;
        }

        // ---- expand 24 packed bits -> 24 floats, 6 x float4 streaming store ----
        const int i = block_start + t;
        float4* po = reinterpret_cast<float4*>(out + (size_t)i * 24);
#pragma unroll
        for (int k = 0; k < 6; k++) {
            float4 w;
            w.x = (float)((packed >> (23 - (k * 4 + 0))) & 1u);
            w.y = (float)((packed >> (23 - (k * 4 + 1))) & 1u);
            w.z = (float)((packed >> (23 - (k * 4 + 2))) & 1u);
            w.w = (float)((packed >> (23 - (k * 4 + 3))) & 1u);
            __stcs(po + k, w);
        }
    }
}

extern "C" void kernel_launch(void* const* d_in, const int* in_sizes, int n_in,
                              void* d_out, int out_size)
{
    // Identify inputs by element count — robust to harness input ordering.
    //   q0: 8 | qg: 448 | noise0: N*8 | noise: (G-1)*N*8
    const float* q0 = nullptr;
    const float* qg = nullptr;
    const float* noise0 = nullptr;
    const float* noise = nullptr;
    long long n0_sz = 0;

    for (int k = 0; k < n_in; k++) {
        long long sz = in_sizes[k];
        const float* p = (const float*)d_in[k];
        if (sz == 8) {
            q0 = p;
        } else if (sz == (NGROUPS - 1) * 64) {
            qg = p;
        } else {
            if (noise0 == nullptr) { noise0 = p; n0_sz = sz; }
            else if (sz > n0_sz)   { noise = p; }
            else { noise = noise0; noise0 = p; n0_sz = sz; }
        }
    }

    const int n = (int)(n0_sz / 8);   // N samples
    const int blocks = (n + NTHREADS - 1) / NTHREADS;
    fd_sample_kernel<<<blocks, NTHREADS>>>(q0, qg, noise0, noise,
                                           (float*)d_out, n);
}

// round 8
// speedup vs baseline: 1.0198x; 1.0122x over previous
#include <cuda_runtime.h>
#include <cstdint>

#define NGROUPS 8
#define NTHREADS 128
#define TILE 128                        // samples per tile (1 per thread)
#define DEPTH 3                         // pipeline stages
#define STAGE_FLOATS (NGROUPS * TILE * 8)   // 8192 floats = 32KB per stage

// dynamic smem layout:
//   [0, DEPTH*32KB)            : noise stages
//   then 8 floats              : q0 table
//   then 448 floats            : qg tables
//   then DEPTH * u64           : mbarriers
#define SMEM_BYTES (DEPTH * STAGE_FLOATS * 4 + (8 + 448) * 4 + DEPTH * 8)

__device__ __forceinline__ void mbar_wait(uint32_t mbar, unsigned int parity)
{
    unsigned int done;
    asm volatile(
        "{\n\t.reg .pred p;\n\t"
        "mbarrier.try_wait.parity.acquire.cta.shared::cta.b64 p, [%1], %2;\n\t"
        "selp.b32 %0, 1, 0, p;\n\t}"
        : "=r"(done) : "r"(mbar), "r"(parity) : "memory");
    while (!done) {
        asm volatile(
            "{\n\t.reg .pred p;\n\t"
            "mbarrier.try_wait.parity.acquire.cta.shared::cta.b64 p, [%1], %2, 0x989680;\n\t"
            "selp.b32 %0, 1, 0, p;\n\t}"
            : "=r"(done) : "r"(mbar), "r"(parity) : "memory");
    }
}

__global__ void __launch_bounds__(NTHREADS)
fd_sample_kernel(const float* __restrict__ q0,
                 const float* __restrict__ qg,
                 const float* __restrict__ noise0,
                 const float* __restrict__ noise,
                 float* __restrict__ out,
                 int n)
{
    extern __shared__ __align__(128) unsigned char dsm[];
    float* s_noise = reinterpret_cast<float*>(dsm);                 // DEPTH stages
    float* s_q0    = s_noise + DEPTH * STAGE_FLOATS;                // 8
    float* s_qg    = s_q0 + 8;                                      // 448
    unsigned long long* s_mbar =
        reinterpret_cast<unsigned long long*>(s_qg + 448);          // DEPTH

    const int t = threadIdx.x;
    const int ntiles = (n + TILE - 1) / TILE;
    const size_t gstride = (size_t)n * 8;

    if (t == 0) {
#pragma unroll
        for (int s = 0; s < DEPTH; s++) {
            uint32_t mb = (uint32_t)__cvta_generic_to_shared(&s_mbar[s]);
            asm volatile("mbarrier.init.shared.b64 [%0], %1;"
                         :: "r"(mb), "r"(1) : "memory");
        }
    }
    for (int k = t; k < 8; k += NTHREADS) s_q0[k] = q0[k];
    for (int k = t; k < (NGROUPS - 1) * 64; k += NTHREADS) s_qg[k] = qg[k];
    __syncthreads();   // mbarrier init + tables visible

    // ---- issue helper (thread 0 only): 8 bulk copies for one tile ----
    auto issue_tile = [&](int tile, int stage) {
        const int bstart = tile * TILE;
        const int nrem = min(TILE, n - bstart);
        const unsigned int gbytes = (unsigned int)nrem * 32u;
        uint32_t mb = (uint32_t)__cvta_generic_to_shared(&s_mbar[stage]);
        asm volatile("mbarrier.arrive.expect_tx.shared.b64 _, [%0], %1;"
                     :: "r"(mb), "r"(gbytes * NGROUPS) : "memory");
        float* sbase = s_noise + stage * STAGE_FLOATS;
        {
            uint32_t dst = (uint32_t)__cvta_generic_to_shared(sbase);
            const float* src = noise0 + (size_t)bstart * 8;
            asm volatile(
                "cp.async.bulk.shared::cta.global.mbarrier::complete_tx::bytes "
                "[%0], [%1], %2, [%3];"
                :: "r"(dst), "l"(src), "r"(gbytes), "r"(mb) : "memory");
        }
#pragma unroll
        for (int g = 1; g < NGROUPS; g++) {
            uint32_t dst = (uint32_t)__cvta_generic_to_shared(sbase + g * TILE * 8);
            const float* src = noise + (size_t)(g - 1) * gstride + (size_t)bstart * 8;
            asm volatile(
                "cp.async.bulk.shared::cta.global.mbarrier::complete_tx::bytes "
                "[%0], [%1], %2, [%3];"
                :: "r"(dst), "l"(src), "r"(gbytes), "r"(mb) : "memory");
        }
    };

    // ---- prologue: fill the pipeline ----
    if (t == 0) {
#pragma unroll
        for (int j = 0; j < DEPTH; j++) {
            int tile = blockIdx.x + j * gridDim.x;
            if (tile < ntiles) issue_tile(tile, j);
        }
    }

    // ---- steady state ----
    for (int j = 0; ; j++) {
        const int tile = blockIdx.x + j * gridDim.x;
        if (tile >= ntiles) break;
        const int stage = j % DEPTH;
        const unsigned int parity = (unsigned int)(j / DEPTH) & 1u;

        uint32_t mb = (uint32_t)__cvta_generic_to_shared(&s_mbar[stage]);
        mbar_wait(mb, parity);

        const int bstart = tile * TILE;
        const int nrem = min(TILE, n - bstart);
        if (t < nrem) {
            const float* sbase = s_noise + stage * STAGE_FLOATS;
            unsigned int packed = 0;
            int best = 0;
#pragma unroll
            for (int g = 0; g < NGROUPS; g++) {
                // group 0 uses q0; g>=1 uses slice qg[g-1][best]
                // (previous argmax index IS the flattened conditioning index)
                const float* tbl = (g == 0) ? s_q0 : &s_qg[(g - 1) * 64 + best * 8];
                const float4* pv =
                    reinterpret_cast<const float4*>(sbase + g * TILE * 8 + t * 8);
                float4 a = pv[0];
                float4 b = pv[1];
                float v[8];
                v[0] = a.x; v[1] = a.y; v[2] = a.z; v[3] = a.w;
                v[4] = b.x; v[5] = b.y; v[6] = b.z; v[7] = b.w;

                int nb = 0;
                float nbv = v[0] + tbl[0];
#pragma unroll
                for (int jj = 1; jj < 8; jj++) {
                    float x = v[jj] + tbl[jj];
                    if (x > nbv) { nbv = x; nb = jj; }   // strict > == first-max
                }
                best = nb;
                packed = (packed << 3) | (unsigned int)best;
            }

            float4* po = reinterpret_cast<float4*>(out + (size_t)(bstart + t) * 24);
#pragma unroll
            for (int k = 0; k < 6; k++) {
                float4 w;
                w.x = (float)((packed >> (23 - (k * 4 + 0))) & 1u);
                w.y = (float)((packed >> (23 - (k * 4 + 1))) & 1u);
                w.z = (float)((packed >> (23 - (k * 4 + 2))) & 1u);
                w.w = (float)((packed >> (23 - (k * 4 + 3))) & 1u);
                __stcs(po + k, w);
            }
        }

        __syncthreads();   // all consumers done with this stage's smem
        if (t == 0) {
            const int tile_next = blockIdx.x + (j + DEPTH) * gridDim.x;
            if (tile_next < ntiles) issue_tile(tile_next, stage);
        }
    }
}

extern "C" void kernel_launch(void* const* d_in, const int* in_sizes, int n_in,
                              void* d_out, int out_size)
{
    // Identify inputs by element count — robust to harness input ordering.
    //   q0: 8 | qg: 448 | noise0: N*8 | noise: (G-1)*N*8
    const float* q0 = nullptr;
    const float* qg = nullptr;
    const float* noise0 = nullptr;
    const float* noise = nullptr;
    long long n0_sz = 0;

    for (int k = 0; k < n_in; k++) {
        long long sz = in_sizes[k];
        const float* p = (const float*)d_in[k];
        if (sz == 8) {
            q0 = p;
        } else if (sz == (NGROUPS - 1) * 64) {
            qg = p;
        } else {
            if (noise0 == nullptr) { noise0 = p; n0_sz = sz; }
            else if (sz > n0_sz)   { noise = p; }
            else { noise = noise0; noise0 = p; n0_sz = sz; }
        }
    }

    const int n = (int)(n0_sz / 8);   // N samples
    const int ntiles = (n + TILE - 1) / TILE;

    cudaFuncSetAttribute(fd_sample_kernel,
                         cudaFuncAttributeMaxDynamicSharedMemorySize, SMEM_BYTES);

    int blocks = 2 * 148;              // persistent: 2 CTAs per SM
    if (blocks > ntiles) blocks = ntiles;
    fd_sample_kernel<<<blocks, NTHREADS, SMEM_BYTES>>>(q0, qg, noise0, noise,
                                                       (float*)d_out, n);
}